// round 1
// baseline (speedup 1.0000x reference)
#include <cuda_runtime.h>

// SSIM loss, B=64, 1x512x512 fp32, 11x11 uniform box filter, zero padding.
// Strategy: one warp owns a full 512-wide row strip (16 cols/lane).
//  - vertical running box sums per column in registers (add entering row,
//    subtract leaving row re-read from L2)
//  - horizontal sliding window per lane, +-5 col halo via warp shuffles
//  - SSIM map + per-thread accumulate, warp reduce, atomicAdd(double)
// Three launches: reset accumulator, main, finalize. All graph-capturable.

namespace {
constexpr int Hh = 512;
constexpr int Ww = 512;
constexpr int Bb = 64;
constexpr int CHUNK = 32;                 // output rows per warp
constexpr int NCHUNK = Hh / CHUNK;        // 16
constexpr float C1c = 0.01f * 0.01f;
constexpr float C2c = 0.03f * 0.03f;
constexpr float INV121 = 1.0f / 121.0f;
}

__device__ double g_acc;

__global__ void k_reset() { g_acc = 0.0; }

__global__ void k_final(float* out) {
    out[0] = (float)(1.0 - g_acc * (1.0 / ((double)Bb * Hh * Ww)));
}

__global__ void k_ssim(const float* __restrict__ X, const float* __restrict__ Y) {
    const int gwarp = (blockIdx.x * blockDim.x + threadIdx.x) >> 5;
    const int lane  = threadIdx.x & 31;
    const int batch = gwarp >> 4;               // / NCHUNK (=16)
    const int chunk = gwarp & (NCHUNK - 1);
    const int row0  = chunk * CHUNK;
    const int c0    = lane << 4;                // 16 cols per lane
    const float* xb = X + batch * (Hh * Ww) + c0;
    const float* yb = Y + batch * (Hh * Ww) + c0;

    // Vertical running sums for 5 channels, 16 columns each (registers).
    float vx[16], vy[16], vxx[16], vyy[16], vxy[16];
#pragma unroll
    for (int k = 0; k < 16; k++) { vx[k] = vy[k] = vxx[k] = vyy[k] = vxy[k] = 0.f; }

    const int lvmin  = (row0 - 5 > 0) ? (row0 - 5) : 0;
    const float lmask = (lane == 0)  ? 0.f : 1.f;   // left image border -> zero pad
    const float rmask = (lane == 31) ? 0.f : 1.f;   // right image border -> zero pad
    float acc = 0.f;

#define VADD(k, xs, ys) do { float _x=(xs), _y=(ys); \
    vx[k]+=_x; vy[k]+=_y; \
    vxx[k]=fmaf(_x,_x,vxx[k]); vyy[k]=fmaf(_y,_y,vyy[k]); vxy[k]=fmaf(_x,_y,vxy[k]); } while(0)
#define VSUB(k, xs, ys) do { float _x=(xs), _y=(ys); \
    vx[k]-=_x; vy[k]-=_y; \
    vxx[k]=fmaf(-_x,_x,vxx[k]); vyy[k]=fmaf(-_y,_y,vyy[k]); vxy[k]=fmaf(-_x,_y,vxy[k]); } while(0)
#define ROW_APPLY(OP) \
    OP(0,a0.x,b0.x);  OP(1,a0.y,b0.y);  OP(2,a0.z,b0.z);  OP(3,a0.w,b0.w); \
    OP(4,a1.x,b1.x);  OP(5,a1.y,b1.y);  OP(6,a1.z,b1.z);  OP(7,a1.w,b1.w); \
    OP(8,a2.x,b2.x);  OP(9,a2.y,b2.y);  OP(10,a2.z,b2.z); OP(11,a2.w,b2.w); \
    OP(12,a3.x,b3.x); OP(13,a3.y,b3.y); OP(14,a3.z,b3.z); OP(15,a3.w,b3.w);

    for (int ri = row0 - 5; ri <= row0 + CHUNK + 4; ++ri) {
        // entering row
        if (ri >= 0 && ri < Hh) {
            const float4* xr = reinterpret_cast<const float4*>(xb + ri * Ww);
            const float4* yr = reinterpret_cast<const float4*>(yb + ri * Ww);
            float4 a0 = xr[0], a1 = xr[1], a2 = xr[2], a3 = xr[3];
            float4 b0 = yr[0], b1 = yr[1], b2 = yr[2], b3 = yr[3];
            ROW_APPLY(VADD)
        }
        // leaving row (only rows that were actually accumulated)
        const int lv = ri - 11;
        if (lv >= lvmin) {
            const float4* xr = reinterpret_cast<const float4*>(xb + lv * Ww);
            const float4* yr = reinterpret_cast<const float4*>(yb + lv * Ww);
            float4 a0 = xr[0], a1 = xr[1], a2 = xr[2], a3 = xr[3];
            float4 b0 = yr[0], b1 = yr[1], b2 = yr[2], b3 = yr[3];
            ROW_APPLY(VSUB)
        }
        // output row ro = ri - 5 once the window is full
        if (ri >= row0 + 5) {
            // halo exchange: left needs lane-1's cols 11..15, right needs lane+1's cols 0..4
            float lx[5], ly[5], lxx[5], lyy[5], lxy[5];
            float rx[5], ry[5], rxx[5], ryy[5], rxy[5];
#pragma unroll
            for (int j = 0; j < 5; j++) {
                lx[j]  = __shfl_up_sync(0xffffffffu, vx[11+j],  1) * lmask;
                ly[j]  = __shfl_up_sync(0xffffffffu, vy[11+j],  1) * lmask;
                lxx[j] = __shfl_up_sync(0xffffffffu, vxx[11+j], 1) * lmask;
                lyy[j] = __shfl_up_sync(0xffffffffu, vyy[11+j], 1) * lmask;
                lxy[j] = __shfl_up_sync(0xffffffffu, vxy[11+j], 1) * lmask;
                rx[j]  = __shfl_down_sync(0xffffffffu, vx[j],  1) * rmask;
                ry[j]  = __shfl_down_sync(0xffffffffu, vy[j],  1) * rmask;
                rxx[j] = __shfl_down_sync(0xffffffffu, vxx[j], 1) * rmask;
                ryy[j] = __shfl_down_sync(0xffffffffu, vyy[j], 1) * rmask;
                rxy[j] = __shfl_down_sync(0xffffffffu, vxy[j], 1) * rmask;
            }
#define HINIT(ch) (l##ch[0]+l##ch[1]+l##ch[2]+l##ch[3]+l##ch[4] \
                  +v##ch[0]+v##ch[1]+v##ch[2]+v##ch[3]+v##ch[4]+v##ch[5])
            float sx  = HINIT(x);
            float sy  = HINIT(y);
            float sxx = HINIT(xx);
            float syy = HINIT(yy);
            float sxy = HINIT(xy);
#undef HINIT
            // sliding: S_{j+1} = S_j + val[j+6] - val[j-5]
#define HADD(ch) ( (j+6 <= 15) ? v##ch[(j+6)&15] : r##ch[((j-10)<0)?0:(j-10)] )
#define HSUB(ch) ( (j >= 5)    ? v##ch[(j-5)&15] : l##ch[(j<5)?j:4] )
#pragma unroll
            for (int j = 0; j < 16; j++) {
                float mux = sx  * INV121;
                float muy = sy  * INV121;
                float exx = sxx * INV121;
                float eyy = syy * INV121;
                float exy = sxy * INV121;
                float mxy = mux * muy;
                float m2  = fmaf(mux, mux, muy * muy);
                float num = fmaf(2.f, mxy, C1c) * fmaf(2.f, exy - mxy, C2c);
                float den = (m2 + C1c) * ((exx + eyy) - m2 + C2c);
                acc += __fdividef(num, den);
                if (j < 15) {
                    sx  += HADD(x)  - HSUB(x);
                    sy  += HADD(y)  - HSUB(y);
                    sxx += HADD(xx) - HSUB(xx);
                    syy += HADD(yy) - HSUB(yy);
                    sxy += HADD(xy) - HSUB(xy);
                }
            }
#undef HADD
#undef HSUB
        }
    }

    // warp reduce, one double atomic per warp
#pragma unroll
    for (int off = 16; off; off >>= 1)
        acc += __shfl_xor_sync(0xffffffffu, acc, off);
    if (lane == 0) atomicAdd(&g_acc, (double)acc);
}

extern "C" void kernel_launch(void* const* d_in, const int* in_sizes, int n_in,
                              void* d_out, int out_size) {
    const float* x = (const float*)d_in[0];
    const float* y = (const float*)d_in[1];
    (void)in_sizes; (void)n_in; (void)out_size;
    k_reset<<<1, 1>>>();
    const int total_warps = Bb * NCHUNK;          // 1024
    k_ssim<<<total_warps / 8, 256>>>(x, y);       // 128 CTAs x 8 warps
    k_final<<<1, 1>>>((float*)d_out);
}